// round 15
// baseline (speedup 1.0000x reference)
#include <cuda_runtime.h>
#include <cuda_bf16.h>
#include <math.h>
#include <stdint.h>

#define NT 8192
#define DM 1024
#define FF 4096
#define NE 8
#define TOTAL_ROWS (NT * 2)

// packed smem: per stage A[128 rows][9 uint4] + B[128 rows][9 uint4]
// row = 8 data uint4 (32 k as 16 hi/lo bf16x2 pairs) + 1 pad uint4
#define TROW 9
#define HDR4 128                       // 2048 B header (stok/sbias/swt)
#define TILE4 (128 * TROW)             // 1152 uint4
#define STAGE4 (2 * TILE4)             // A + B
#define SMEM_BYTES ((HDR4 + 2 * STAGE4) * 16)   // 75776 B

// ---------------- scratch (device globals; no runtime alloc) ----------------
__device__ int   g_cnt[NE];
__device__ int   g_off[NE];
__device__ int   g_tok[NE * NT];
__device__ float g_w  [NE * NT];
// padded by 128 rows so OOB-tile A loads in GEMM2 stay in-bounds
__device__ __align__(16) float g_h[(size_t)(TOTAL_ROWS + 128) * FF];
// fp32 transposed weights: W1t[e][n][k], W2t[e][n][k]
__device__ __align__(16) float g_w1t[(size_t)NE * FF * DM];
__device__ __align__(16) float g_w2t[(size_t)NE * DM * FF];

// ---------------- mma.sync (validated R7/R12/R14) ----------------
__device__ __forceinline__ void mma_bf16(float (&d)[4], const uint32_t (&a)[4],
                                         uint32_t b0, uint32_t b1) {
    asm volatile("mma.sync.aligned.m16n8k16.row.col.f32.bf16.bf16.f32 "
        "{%0,%1,%2,%3}, {%4,%5,%6,%7}, {%8,%9}, {%0,%1,%2,%3};"
        : "+f"(d[0]), "+f"(d[1]), "+f"(d[2]), "+f"(d[3])
        : "r"(a[0]), "r"(a[1]), "r"(a[2]), "r"(a[3]), "r"(b0), "r"(b1));
}

// split two fp32 into packed bf16x2 hi and lo (identical arithmetic to R12/R14)
__device__ __forceinline__ void split2(float v0, float v1, uint32_t& hi, uint32_t& lo) {
    __nv_bfloat162 h = __floats2bfloat162_rn(v0, v1);
    float r0 = v0 - __bfloat162float(h.x);
    float r1 = v1 - __bfloat162float(h.y);
    __nv_bfloat162 l = __floats2bfloat162_rn(r0, r1);
    hi = *reinterpret_cast<uint32_t*>(&h);
    lo = *reinterpret_cast<uint32_t*>(&l);
}

// pack 16 consecutive fp32 k-values (4 float4) into 4 interleaved uint4s:
// slot q = {hi(pair q), hi(pair q+4), lo(pair q), lo(pair q+4)}, pair p = k 2p,2p+1
__device__ __forceinline__ void pack16(uint4 (&dst)[4], const float4 (&v)[4]) {
    const float f[16] = {v[0].x, v[0].y, v[0].z, v[0].w,
                         v[1].x, v[1].y, v[1].z, v[1].w,
                         v[2].x, v[2].y, v[2].z, v[2].w,
                         v[3].x, v[3].y, v[3].z, v[3].w};
#pragma unroll
    for (int q = 0; q < 4; q++) {
        uint32_t h0, l0, h1, l1;
        split2(f[2 * q],     f[2 * q + 1], h0, l0);
        split2(f[2 * q + 8], f[2 * q + 9], h1, l1);
        dst[q].x = h0; dst[q].y = h1; dst[q].z = l0; dst[q].w = l1;
    }
}

// ---------------- zero counts + output ----------------
__global__ void zero_kernel(float* __restrict__ out) {
    int i = blockIdx.x * blockDim.x + threadIdx.x;
    if (i < NE) g_cnt[i] = 0;
    float4* o4 = reinterpret_cast<float4*>(out);
    if (i < NT * DM / 4) o4[i] = make_float4(0.f, 0.f, 0.f, 0.f);
}

// ---------------- gate (validated R1) ----------------
__global__ void gate_kernel(const float* __restrict__ x,
                            const float* __restrict__ Wg,
                            const float* __restrict__ bg) {
    int gtid = blockIdx.x * blockDim.x + threadIdx.x;
    int t = gtid >> 5, lane = gtid & 31;
    if (t >= NT) return;
    const float* xr = x + (size_t)t * DM;
    float acc[NE];
#pragma unroll
    for (int e = 0; e < NE; e++) acc[e] = 0.f;
    for (int k = lane; k < DM; k += 32) {
        float xv = xr[k];
        const float* wr = Wg + k * NE;
#pragma unroll
        for (int e = 0; e < NE; e++) acc[e] += xv * wr[e];
    }
#pragma unroll
    for (int s = 16; s > 0; s >>= 1)
#pragma unroll
        for (int e = 0; e < NE; e++) acc[e] += __shfl_xor_sync(0xffffffffu, acc[e], s);
    if (lane == 0) {
#pragma unroll
        for (int e = 0; e < NE; e++) acc[e] += bg[e];
        float mx = acc[0];
#pragma unroll
        for (int e = 1; e < NE; e++) mx = fmaxf(mx, acc[e]);
        float s = 0.f;
#pragma unroll
        for (int e = 0; e < NE; e++) { acc[e] = expf(acc[e] - mx); s += acc[e]; }
        float inv = 1.f / s;
#pragma unroll
        for (int e = 0; e < NE; e++) acc[e] *= inv;
        int i0 = 0;
#pragma unroll
        for (int e = 1; e < NE; e++) if (acc[e] > acc[i0]) i0 = e;
        int i1 = (i0 == 0) ? 1 : 0;
#pragma unroll
        for (int e = 0; e < NE; e++) if (e != i0 && acc[e] > acc[i1]) i1 = e;
        float s2 = acc[i0] + acc[i1] + 1e-9f;
        int p0 = atomicAdd(&g_cnt[i0], 1);
        g_tok[i0 * NT + p0] = t;  g_w[i0 * NT + p0] = acc[i0] / s2;
        int p1 = atomicAdd(&g_cnt[i1], 1);
        g_tok[i1 * NT + p1] = t;  g_w[i1 * NT + p1] = acc[i1] / s2;
    }
}

__global__ void offsets_kernel() {
    if (threadIdx.x == 0 && blockIdx.x == 0) {
        int s = 0;
#pragma unroll
        for (int e = 0; e < NE; e++) { g_off[e] = s; s += g_cnt[e]; }
    }
}

// ---------------- fp32 transpose: in [E][R][C] -> out [E][C][R] (validated R14) ----
__global__ void wtrans(const float* __restrict__ in, float* __restrict__ out,
                       int R, int C) {
    __shared__ float t[32][33];
    int e = blockIdx.z, c0 = blockIdx.x * 32, r0 = blockIdx.y * 32;
    const float* ie = in + (size_t)e * R * C;
    float* oe = out + (size_t)e * R * C;
    int tx = threadIdx.x & 31, ty = threadIdx.x >> 5;   // 32 x 8
#pragma unroll
    for (int i = 0; i < 4; i++)
        t[ty + i * 8][tx] = ie[(size_t)(r0 + ty + i * 8) * C + c0 + tx];
    __syncthreads();
#pragma unroll
    for (int i = 0; i < 4; i++)
        oe[(size_t)(c0 + ty + i * 8) * R + r0 + tx] = t[tx][ty + i * 8];
}

// ---- compute one k32 stage; MMAs emitted in 3 sweeps so same-accumulator
// ---- dependencies are spaced 16 independent instructions apart.
// ---- Per-accumulator add order (hh, lh, hl per (g,s)) is unchanged -> bit-identical.
__device__ __forceinline__ void compute_stage32(const uint4* __restrict__ A4,
                                                const uint4* __restrict__ B4,
                                                int wm, int wn, int lid,
                                                float (&acc)[2][8][4]) {
    const int qr = lid >> 2, q = lid & 3;
#pragma unroll
    for (int s = 0; s < 2; s++) {
        uint32_t ah[2][4], al[2][4];
#pragma unroll
        for (int mf = 0; mf < 2; mf++) {
            uint4 U1 = A4[(wm + mf * 16 + qr) * TROW + s * 4 + q];
            uint4 U2 = A4[(wm + mf * 16 + qr + 8) * TROW + s * 4 + q];
            ah[mf][0] = U1.x; ah[mf][1] = U2.x; ah[mf][2] = U1.y; ah[mf][3] = U2.y;
            al[mf][0] = U1.z; al[mf][1] = U2.z; al[mf][2] = U1.w; al[mf][3] = U2.w;
        }
        // sweep 1: hi*hi
#pragma unroll
        for (int g = 0; g < 8; g++) {
            uint4 V = B4[(wn + g * 8 + qr) * TROW + s * 4 + q];
            mma_bf16(acc[0][g], ah[0], V.x, V.y);
            mma_bf16(acc[1][g], ah[1], V.x, V.y);
        }
        // sweep 2: lo*hi
#pragma unroll
        for (int g = 0; g < 8; g++) {
            uint4 V = B4[(wn + g * 8 + qr) * TROW + s * 4 + q];
            mma_bf16(acc[0][g], al[0], V.x, V.y);
            mma_bf16(acc[1][g], al[1], V.x, V.y);
        }
        // sweep 3: hi*lo
#pragma unroll
        for (int g = 0; g < 8; g++) {
            uint4 V = B4[(wn + g * 8 + qr) * TROW + s * 4 + q];
            mma_bf16(acc[0][g], ah[0], V.z, V.w);
            mma_bf16(acc[1][g], ah[1], V.z, V.w);
        }
    }
}

// ================= GEMM1: h = gelu(x[tok] @ W1 + b1) =================
__global__ __launch_bounds__(256, 2) void ffn1_hmma(const float* __restrict__ x,
                                                    const float* __restrict__ b1) {
    extern __shared__ uint4 sm4[];
    const int e = blockIdx.z;
    const int cnt = g_cnt[e];
    const int mbase = blockIdx.y * 128;
    if (mbase >= cnt) return;
    const int nbase = blockIdx.x * 128;

    const int tid = threadIdx.x, wid = tid >> 5, lid = tid & 31;
    const int wm = (wid & 3) * 32, wn = (wid >> 2) * 64;

    int*   stok  = reinterpret_cast<int*>(sm4);
    float* sbias = reinterpret_cast<float*>(sm4) + 128;

    if (tid < 128) {
        int mi = mbase + tid;
        stok[tid]  = (mi < cnt) ? g_tok[e * NT + mi] : g_tok[e * NT + mbase];
        sbias[tid] = b1[e * FF + nbase + tid];
    }
    __syncthreads();

    // staging: thread -> (row, khalf); both operands k-consecutive in gmem
    const int row = tid >> 1, khalf = tid & 1;
    const float* arow = x + (size_t)stok[row] * DM + khalf * 16;
    const float* brow = g_w1t + (size_t)e * FF * DM + (size_t)(nbase + row) * DM + khalf * 16;
    const int slot = row * TROW + khalf * 4;

    float acc[2][8][4];
#pragma unroll
    for (int i = 0; i < 2; i++)
#pragma unroll
        for (int j = 0; j < 8; j++)
#pragma unroll
            for (int k = 0; k < 4; k++) acc[i][j][k] = 0.f;

    float4 ra[4], rb[4];
#pragma unroll
    for (int j = 0; j < 4; j++) {
        ra[j] = *reinterpret_cast<const float4*>(arow + j * 4);
        rb[j] = *reinterpret_cast<const float4*>(brow + j * 4);
    }

    int buf = 0;
    for (int kt = 0; kt < DM; kt += 32) {
        uint4* As = sm4 + HDR4 + buf * STAGE4;
        uint4* Bs = As + TILE4;
        uint4 pa[4], pb[4];
        pack16(pa, ra);
        pack16(pb, rb);
#pragma unroll
        for (int q = 0; q < 4; q++) { As[slot + q] = pa[q]; Bs[slot + q] = pb[q]; }
        __syncthreads();
        if (kt + 32 < DM) {   // prefetch next stage; overlaps compute
#pragma unroll
            for (int j = 0; j < 4; j++) {
                ra[j] = *reinterpret_cast<const float4*>(arow + kt + 32 + j * 4);
                rb[j] = *reinterpret_cast<const float4*>(brow + kt + 32 + j * 4);
            }
        }
        compute_stage32(sm4 + HDR4 + buf * STAGE4,
                        sm4 + HDR4 + buf * STAGE4 + TILE4, wm, wn, lid, acc);
        buf ^= 1;
    }

    // epilogue: bias + exact GELU -> fp32 h (validated R7/R12)
    const int hoff = g_off[e];
    const int qr = lid >> 2, c2 = (lid & 3) * 2;
#pragma unroll
    for (int mf = 0; mf < 2; mf++)
#pragma unroll
        for (int half = 0; half < 2; half++) {
            int m = mbase + wm + mf * 16 + qr + half * 8;
            if (m < cnt) {
                float* hr = g_h + (size_t)(hoff + m) * FF + nbase;
#pragma unroll
                for (int g = 0; g < 8; g++) {
                    int cl = wn + g * 8 + c2;
                    float v0 = acc[mf][g][half * 2]     + sbias[cl];
                    float v1 = acc[mf][g][half * 2 + 1] + sbias[cl + 1];
                    hr[cl]     = 0.5f * v0 * (1.f + erff(v0 * 0.70710678118654752f));
                    hr[cl + 1] = 0.5f * v1 * (1.f + erff(v1 * 0.70710678118654752f));
                }
            }
        }
}

// ================= GEMM2: out[tok] += w * (h @ W2 + b2) =================
__global__ __launch_bounds__(256, 2) void ffn2_hmma(const float* __restrict__ b2,
                                                    float* __restrict__ out) {
    extern __shared__ uint4 sm4[];
    const int e = blockIdx.z;
    const int cnt = g_cnt[e];
    const int mbase = blockIdx.y * 128;
    if (mbase >= cnt) return;
    const int nbase = blockIdx.x * 128;

    const int tid = threadIdx.x, wid = tid >> 5, lid = tid & 31;
    const int wm = (wid & 3) * 32, wn = (wid >> 2) * 64;

    int*   stok  = reinterpret_cast<int*>(sm4);
    float* sbias = reinterpret_cast<float*>(sm4) + 128;
    float* swt   = reinterpret_cast<float*>(sm4) + 256;

    if (tid < 128) {
        int mi = mbase + tid;
        bool v = mi < cnt;
        stok[tid]  = v ? g_tok[e * NT + mi] : 0;
        swt[tid]   = v ? g_w  [e * NT + mi] : 0.f;
        sbias[tid] = b2[e * DM + nbase + tid];
    }
    __syncthreads();

    const int hoff = g_off[e];
    const int row = tid >> 1, khalf = tid & 1;
    const float* arow = g_h + (size_t)(hoff + mbase + row) * FF + khalf * 16;   // padded
    const float* brow = g_w2t + (size_t)e * DM * FF + (size_t)(nbase + row) * FF + khalf * 16;
    const int slot = row * TROW + khalf * 4;

    float acc[2][8][4];
#pragma unroll
    for (int i = 0; i < 2; i++)
#pragma unroll
        for (int j = 0; j < 8; j++)
#pragma unroll
            for (int k = 0; k < 4; k++) acc[i][j][k] = 0.f;

    float4 ra[4], rb[4];
#pragma unroll
    for (int j = 0; j < 4; j++) {
        ra[j] = *reinterpret_cast<const float4*>(arow + j * 4);
        rb[j] = *reinterpret_cast<const float4*>(brow + j * 4);
    }

    int buf = 0;
    for (int kt = 0; kt < FF; kt += 32) {
        uint4* As = sm4 + HDR4 + buf * STAGE4;
        uint4* Bs = As + TILE4;
        uint4 pa[4], pb[4];
        pack16(pa, ra);
        pack16(pb, rb);
#pragma unroll
        for (int q = 0; q < 4; q++) { As[slot + q] = pa[q]; Bs[slot + q] = pb[q]; }
        __syncthreads();
        if (kt + 32 < FF) {
#pragma unroll
            for (int j = 0; j < 4; j++) {
                ra[j] = *reinterpret_cast<const float4*>(arow + kt + 32 + j * 4);
                rb[j] = *reinterpret_cast<const float4*>(brow + kt + 32 + j * 4);
            }
        }
        compute_stage32(sm4 + HDR4 + buf * STAGE4,
                        sm4 + HDR4 + buf * STAGE4 + TILE4, wm, wn, lid, acc);
        buf ^= 1;
    }

    // epilogue: bias + gate-weighted scatter (validated R7/R12)
    const int qr = lid >> 2, c2 = (lid & 3) * 2;
#pragma unroll
    for (int mf = 0; mf < 2; mf++)
#pragma unroll
        for (int half = 0; half < 2; half++) {
            int mloc = wm + mf * 16 + qr + half * 8;
            int m = mbase + mloc;
            if (m < cnt) {
                int   tok = stok[mloc];
                float wv  = swt[mloc];
                float* orow = out + (size_t)tok * DM + nbase;
#pragma unroll
                for (int g = 0; g < 8; g++) {
                    int cl = wn + g * 8 + c2;
                    atomicAdd(&orow[cl],     wv * (acc[mf][g][half * 2]     + sbias[cl]));
                    atomicAdd(&orow[cl + 1], wv * (acc[mf][g][half * 2 + 1] + sbias[cl + 1]));
                }
            }
        }
}

// ---------------------------------------------------------------
extern "C" void kernel_launch(void* const* d_in, const int* in_sizes, int n_in,
                              void* d_out, int out_size) {
    const float* x  = (const float*)d_in[0];
    const float* Wg = (const float*)d_in[1];
    const float* bg = (const float*)d_in[2];
    const float* W1 = (const float*)d_in[3];
    const float* b1 = (const float*)d_in[4];
    const float* W2 = (const float*)d_in[5];
    const float* b2 = (const float*)d_in[6];
    float* out = (float*)d_out;

    cudaFuncSetAttribute(ffn1_hmma, cudaFuncAttributeMaxDynamicSharedMemorySize, SMEM_BYTES);
    cudaFuncSetAttribute(ffn2_hmma, cudaFuncAttributeMaxDynamicSharedMemorySize, SMEM_BYTES);

    float* w1t; cudaGetSymbolAddress((void**)&w1t, g_w1t);
    float* w2t; cudaGetSymbolAddress((void**)&w2t, g_w2t);

    zero_kernel<<<NT * DM / 4 / 256, 256>>>(out);
    gate_kernel<<<1024, 256>>>(x, Wg, bg);
    offsets_kernel<<<1, 32>>>();
    // W1 [E][DM][FF] -> W1t [E][FF][DM]
    wtrans<<<dim3(FF / 32, DM / 32, NE), 256>>>(W1, w1t, DM, FF);
    // W2 [E][FF][DM] -> W2t [E][DM][FF]
    wtrans<<<dim3(DM / 32, FF / 32, NE), 256>>>(W2, w2t, FF, DM);

    ffn1_hmma<<<dim3(FF / 128, NT / 128, NE), 256, SMEM_BYTES>>>(x, b1);
    ffn2_hmma<<<dim3(DM / 128, NT / 128, NE), 256, SMEM_BYTES>>>(b2, out);
}

// round 16
// speedup vs baseline: 1.1743x; 1.1743x over previous
#include <cuda_runtime.h>
#include <cuda_fp16.h>
#include <math.h>
#include <stdint.h>

#define NT 8192
#define DM 1024
#define FF 4096
#define NE 8
#define TOTAL_ROWS (NT * 2)
#define KCH1 (DM / 32)
#define KCH2 (FF / 32)

// packed smem: per stage A[128 rows][9 uint4] (fp16 hi+lo) + B[128 rows][5 uint4] (fp16 hi)
#define TROW 9
#define BROW 5
#define HDR4 128                        // 2048 B header
#define ATILE4 (128 * TROW)             // 1152 uint4
#define BTILE4 (128 * BROW)             // 640 uint4
#define STAGE4 (ATILE4 + BTILE4)        // 1792 uint4
#define SMEM_BYTES ((HDR4 + 2 * STAGE4) * 16)   // 59392 B

// ---------------- scratch (device globals; no runtime alloc) ----------------
__device__ int   g_cnt[NE];
__device__ int   g_off[NE];
__device__ int   g_tok[NE * NT];
__device__ float g_w  [NE * NT];
// padded by 128 rows so OOB-tile A loads in GEMM2 stay in-bounds
__device__ __align__(16) float g_h[(size_t)(TOTAL_ROWS + 128) * FF];
// packed fp16 weights, fragment-ordered: [e][n][k/32][4] uint4
// slot q = {pair(2q,2q+1), pair(2q+8,..), pair(2q+16,..), pair(2q+24,..)}
__device__ uint4 g_w1pk[(size_t)NE * FF * KCH1 * 4];
__device__ uint4 g_w2pk[(size_t)NE * DM * KCH2 * 4];

// ---------------- fp16 mma.sync ----------------
__device__ __forceinline__ void mma_f16(float (&d)[4], const uint32_t (&a)[4],
                                        uint32_t b0, uint32_t b1) {
    asm volatile("mma.sync.aligned.m16n8k16.row.col.f32.f16.f16.f32 "
        "{%0,%1,%2,%3}, {%4,%5,%6,%7}, {%8,%9}, {%0,%1,%2,%3};"
        : "+f"(d[0]), "+f"(d[1]), "+f"(d[2]), "+f"(d[3])
        : "r"(a[0]), "r"(a[1]), "r"(a[2]), "r"(a[3]), "r"(b0), "r"(b1));
}

// split two fp32 into packed fp16x2 hi and lo (v = hi + lo, ~22-bit mantissa)
__device__ __forceinline__ void split2h(float v0, float v1, uint32_t& hi, uint32_t& lo) {
    __half2 h = __floats2half2_rn(v0, v1);
    float r0 = v0 - __half2float(__low2half(h));
    float r1 = v1 - __half2float(__high2half(h));
    __half2 l = __floats2half2_rn(r0, r1);
    hi = *reinterpret_cast<uint32_t*>(&h);
    lo = *reinterpret_cast<uint32_t*>(&l);
}

// pack 16 consecutive fp32 k (4 float4) into 4 uint4: slot q = {hi(q),hi(q+4),lo(q),lo(q+4)}
__device__ __forceinline__ void pack16h(uint4 (&dst)[4], const float4 (&v)[4]) {
    const float f[16] = {v[0].x, v[0].y, v[0].z, v[0].w,
                         v[1].x, v[1].y, v[1].z, v[1].w,
                         v[2].x, v[2].y, v[2].z, v[2].w,
                         v[3].x, v[3].y, v[3].z, v[3].w};
#pragma unroll
    for (int q = 0; q < 4; q++) {
        uint32_t h0, l0, h1, l1;
        split2h(f[2 * q],     f[2 * q + 1], h0, l0);
        split2h(f[2 * q + 8], f[2 * q + 9], h1, l1);
        dst[q].x = h0; dst[q].y = h1; dst[q].z = l0; dst[q].w = l1;
    }
}

// ---------------- zero counts + output ----------------
__global__ void zero_kernel(float* __restrict__ out) {
    int i = blockIdx.x * blockDim.x + threadIdx.x;
    if (i < NE) g_cnt[i] = 0;
    float4* o4 = reinterpret_cast<float4*>(out);
    if (i < NT * DM / 4) o4[i] = make_float4(0.f, 0.f, 0.f, 0.f);
}

// ---------------- gate (validated R1) ----------------
__global__ void gate_kernel(const float* __restrict__ x,
                            const float* __restrict__ Wg,
                            const float* __restrict__ bg) {
    int gtid = blockIdx.x * blockDim.x + threadIdx.x;
    int t = gtid >> 5, lane = gtid & 31;
    if (t >= NT) return;
    const float* xr = x + (size_t)t * DM;
    float acc[NE];
#pragma unroll
    for (int e = 0; e < NE; e++) acc[e] = 0.f;
    for (int k = lane; k < DM; k += 32) {
        float xv = xr[k];
        const float* wr = Wg + k * NE;
#pragma unroll
        for (int e = 0; e < NE; e++) acc[e] += xv * wr[e];
    }
#pragma unroll
    for (int s = 16; s > 0; s >>= 1)
#pragma unroll
        for (int e = 0; e < NE; e++) acc[e] += __shfl_xor_sync(0xffffffffu, acc[e], s);
    if (lane == 0) {
#pragma unroll
        for (int e = 0; e < NE; e++) acc[e] += bg[e];
        float mx = acc[0];
#pragma unroll
        for (int e = 1; e < NE; e++) mx = fmaxf(mx, acc[e]);
        float s = 0.f;
#pragma unroll
        for (int e = 0; e < NE; e++) { acc[e] = expf(acc[e] - mx); s += acc[e]; }
        float inv = 1.f / s;
#pragma unroll
        for (int e = 0; e < NE; e++) acc[e] *= inv;
        int i0 = 0;
#pragma unroll
        for (int e = 1; e < NE; e++) if (acc[e] > acc[i0]) i0 = e;
        int i1 = (i0 == 0) ? 1 : 0;
#pragma unroll
        for (int e = 0; e < NE; e++) if (e != i0 && acc[e] > acc[i1]) i1 = e;
        float s2 = acc[i0] + acc[i1] + 1e-9f;
        int p0 = atomicAdd(&g_cnt[i0], 1);
        g_tok[i0 * NT + p0] = t;  g_w[i0 * NT + p0] = acc[i0] / s2;
        int p1 = atomicAdd(&g_cnt[i1], 1);
        g_tok[i1 * NT + p1] = t;  g_w[i1 * NT + p1] = acc[i1] / s2;
    }
}

__global__ void offsets_kernel() {
    if (threadIdx.x == 0 && blockIdx.x == 0) {
        int s = 0;
#pragma unroll
        for (int e = 0; e < NE; e++) { g_off[e] = s; s += g_cnt[e]; }
    }
}

// ---- transpose + fp16 pack: W [E][R=k][C=n] -> out [e][n][k/32][4] uint4 ----
__global__ void wtrans_pack(const float* __restrict__ in, uint4* __restrict__ out,
                            int R, int C) {
    __shared__ float t[32][33];
    int e = blockIdx.z, c0 = blockIdx.x * 32, r0 = blockIdx.y * 32;
    const float* ie = in + (size_t)e * R * C;
    int tx = threadIdx.x & 31, ty = threadIdx.x >> 5;
#pragma unroll
    for (int i = 0; i < 4; i++)
        t[ty + i * 8][tx] = ie[(size_t)(r0 + ty + i * 8) * C + c0 + tx];   // t[k][n]
    __syncthreads();
    if (threadIdx.x < 128) {
        int nn = threadIdx.x >> 2, q = threadIdx.x & 3;
        __half2 P0 = __floats2half2_rn(t[2 * q][nn],      t[2 * q + 1][nn]);
        __half2 P1 = __floats2half2_rn(t[2 * q + 8][nn],  t[2 * q + 9][nn]);
        __half2 P2 = __floats2half2_rn(t[2 * q + 16][nn], t[2 * q + 17][nn]);
        __half2 P3 = __floats2half2_rn(t[2 * q + 24][nn], t[2 * q + 25][nn]);
        uint4 o;
        o.x = *reinterpret_cast<uint32_t*>(&P0);
        o.y = *reinterpret_cast<uint32_t*>(&P1);
        o.z = *reinterpret_cast<uint32_t*>(&P2);
        o.w = *reinterpret_cast<uint32_t*>(&P3);
        out[(((size_t)e * C + c0 + nn) * (R / 32) + (r0 >> 5)) * 4 + q] = o;
    }
}

// ---- compute one k32 stage: 2-product fp16 (A exact hi+lo, B hi only) ----
// 8 A LDS.128 + 16 B LDS.64 + 64 MMA per warp-stage
__device__ __forceinline__ void compute_stage32(const uint4* __restrict__ A4,
                                                const uint4* __restrict__ B4,
                                                int wm, int wn, int lid,
                                                float (&acc)[2][8][4]) {
    const int qr = lid >> 2, q = lid & 3;
#pragma unroll
    for (int s = 0; s < 2; s++) {
        uint32_t ah[2][4], al[2][4];
#pragma unroll
        for (int mf = 0; mf < 2; mf++) {
            uint4 U1 = A4[(wm + mf * 16 + qr) * TROW + s * 4 + q];
            uint4 U2 = A4[(wm + mf * 16 + qr + 8) * TROW + s * 4 + q];
            ah[mf][0] = U1.x; ah[mf][1] = U2.x; ah[mf][2] = U1.y; ah[mf][3] = U2.y;
            al[mf][0] = U1.z; al[mf][1] = U2.z; al[mf][2] = U1.w; al[mf][3] = U2.w;
        }
#pragma unroll
        for (int g = 0; g < 8; g++) {
            // slot q of row; s selects low/high 8B half of the uint4
            const char* bp = reinterpret_cast<const char*>(
                B4 + (wn + g * 8 + qr) * BROW + q) + s * 8;
            uint2 V = *reinterpret_cast<const uint2*>(bp);
            mma_f16(acc[0][g], ah[0], V.x, V.y);   // ah * wh
            mma_f16(acc[1][g], ah[1], V.x, V.y);
            mma_f16(acc[0][g], al[0], V.x, V.y);   // al * wh
            mma_f16(acc[1][g], al[1], V.x, V.y);
        }
    }
}

// ================= GEMM1: h = gelu(x[tok] @ W1 + b1) =================
__global__ __launch_bounds__(256, 2) void ffn1_hmma(const float* __restrict__ x,
                                                    const float* __restrict__ b1) {
    extern __shared__ uint4 sm4[];
    const int e = blockIdx.z;
    const int cnt = g_cnt[e];
    const int mbase = blockIdx.y * 128;
    if (mbase >= cnt) return;
    const int nbase = blockIdx.x * 128;

    const int tid = threadIdx.x, wid = tid >> 5, lid = tid & 31;
    const int wm = (wid & 3) * 32, wn = (wid >> 2) * 64;

    int*   stok  = reinterpret_cast<int*>(sm4);
    float* sbias = reinterpret_cast<float*>(sm4) + 128;

    if (tid < 128) {
        int mi = mbase + tid;
        stok[tid]  = (mi < cnt) ? g_tok[e * NT + mi] : g_tok[e * NT + mbase];
        sbias[tid] = b1[e * FF + nbase + tid];
    }
    __syncthreads();

    // staging: thread -> (row, kh)
    const int row = tid >> 1, kh = tid & 1;
    const float* arow = x + (size_t)stok[row] * DM + kh * 16;
    const uint4* brow = g_w1pk + ((size_t)e * FF + nbase + row) * (KCH1 * 4) + kh * 2;
    const int aslot = row * TROW + kh * 4;
    const int bslot = row * BROW + kh * 2;

    float acc[2][8][4];
#pragma unroll
    for (int i = 0; i < 2; i++)
#pragma unroll
        for (int j = 0; j < 8; j++)
#pragma unroll
            for (int k = 0; k < 4; k++) acc[i][j][k] = 0.f;

    float4 ra[4];
    uint4  rb[2];
#pragma unroll
    for (int j = 0; j < 4; j++) ra[j] = *reinterpret_cast<const float4*>(arow + j * 4);
    rb[0] = brow[0]; rb[1] = brow[1];

    int buf = 0;
    for (int c = 0; c < KCH1; c++) {
        uint4* As = sm4 + HDR4 + buf * STAGE4;
        uint4* Bs = As + ATILE4;
        uint4 pa[4];
        pack16h(pa, ra);
#pragma unroll
        for (int q = 0; q < 4; q++) As[aslot + q] = pa[q];
        Bs[bslot]     = rb[0];
        Bs[bslot + 1] = rb[1];
        __syncthreads();
        if (c + 1 < KCH1) {   // prefetch next stage; overlaps compute
#pragma unroll
            for (int j = 0; j < 4; j++)
                ra[j] = *reinterpret_cast<const float4*>(arow + (c + 1) * 32 + j * 4);
            rb[0] = brow[(c + 1) * 4];
            rb[1] = brow[(c + 1) * 4 + 1];
        }
        compute_stage32(sm4 + HDR4 + buf * STAGE4,
                        sm4 + HDR4 + buf * STAGE4 + ATILE4, wm, wn, lid, acc);
        buf ^= 1;
    }

    // epilogue: bias + exact GELU -> fp32 h (validated R7/R12)
    const int hoff = g_off[e];
    const int qr = lid >> 2, c2 = (lid & 3) * 2;
#pragma unroll
    for (int mf = 0; mf < 2; mf++)
#pragma unroll
        for (int half = 0; half < 2; half++) {
            int m = mbase + wm + mf * 16 + qr + half * 8;
            if (m < cnt) {
                float* hr = g_h + (size_t)(hoff + m) * FF + nbase;
#pragma unroll
                for (int g = 0; g < 8; g++) {
                    int cl = wn + g * 8 + c2;
                    float v0 = acc[mf][g][half * 2]     + sbias[cl];
                    float v1 = acc[mf][g][half * 2 + 1] + sbias[cl + 1];
                    hr[cl]     = 0.5f * v0 * (1.f + erff(v0 * 0.70710678118654752f));
                    hr[cl + 1] = 0.5f * v1 * (1.f + erff(v1 * 0.70710678118654752f));
                }
            }
        }
}

// ================= GEMM2: out[tok] += w * (h @ W2 + b2) =================
__global__ __launch_bounds__(256, 2) void ffn2_hmma(const float* __restrict__ b2,
                                                    float* __restrict__ out) {
    extern __shared__ uint4 sm4[];
    const int e = blockIdx.z;
    const int cnt = g_cnt[e];
    const int mbase = blockIdx.y * 128;
    if (mbase >= cnt) return;
    const int nbase = blockIdx.x * 128;

    const int tid = threadIdx.x, wid = tid >> 5, lid = tid & 31;
    const int wm = (wid & 3) * 32, wn = (wid >> 2) * 64;

    int*   stok  = reinterpret_cast<int*>(sm4);
    float* sbias = reinterpret_cast<float*>(sm4) + 128;
    float* swt   = reinterpret_cast<float*>(sm4) + 256;

    if (tid < 128) {
        int mi = mbase + tid;
        bool v = mi < cnt;
        stok[tid]  = v ? g_tok[e * NT + mi] : 0;
        swt[tid]   = v ? g_w  [e * NT + mi] : 0.f;
        sbias[tid] = b2[e * DM + nbase + tid];
    }
    __syncthreads();

    const int hoff = g_off[e];
    const int row = tid >> 1, kh = tid & 1;
    const float* arow = g_h + (size_t)(hoff + mbase + row) * FF + kh * 16;   // padded
    const uint4* brow = g_w2pk + ((size_t)e * DM + nbase + row) * (KCH2 * 4) + kh * 2;
    const int aslot = row * TROW + kh * 4;
    const int bslot = row * BROW + kh * 2;

    float acc[2][8][4];
#pragma unroll
    for (int i = 0; i < 2; i++)
#pragma unroll
        for (int j = 0; j < 8; j++)
#pragma unroll
            for (int k = 0; k < 4; k++) acc[i][j][k] = 0.f;

    float4 ra[4];
    uint4  rb[2];
#pragma unroll
    for (int j = 0; j < 4; j++) ra[j] = *reinterpret_cast<const float4*>(arow + j * 4);
    rb[0] = brow[0]; rb[1] = brow[1];

    int buf = 0;
    for (int c = 0; c < KCH2; c++) {
        uint4* As = sm4 + HDR4 + buf * STAGE4;
        uint4* Bs = As + ATILE4;
        uint4 pa[4];
        pack16h(pa, ra);
#pragma unroll
        for (int q = 0; q < 4; q++) As[aslot + q] = pa[q];
        Bs[bslot]     = rb[0];
        Bs[bslot + 1] = rb[1];
        __syncthreads();
        if (c + 1 < KCH2) {
#pragma unroll
            for (int j = 0; j < 4; j++)
                ra[j] = *reinterpret_cast<const float4*>(arow + (c + 1) * 32 + j * 4);
            rb[0] = brow[(c + 1) * 4];
            rb[1] = brow[(c + 1) * 4 + 1];
        }
        compute_stage32(sm4 + HDR4 + buf * STAGE4,
                        sm4 + HDR4 + buf * STAGE4 + ATILE4, wm, wn, lid, acc);
        buf ^= 1;
    }

    // epilogue: bias + gate-weighted scatter (validated R7/R12)
    const int qr = lid >> 2, c2 = (lid & 3) * 2;
#pragma unroll
    for (int mf = 0; mf < 2; mf++)
#pragma unroll
        for (int half = 0; half < 2; half++) {
            int mloc = wm + mf * 16 + qr + half * 8;
            int m = mbase + mloc;
            if (m < cnt) {
                int   tok = stok[mloc];
                float wv  = swt[mloc];
                float* orow = out + (size_t)tok * DM + nbase;
#pragma unroll
                for (int g = 0; g < 8; g++) {
                    int cl = wn + g * 8 + c2;
                    atomicAdd(&orow[cl],     wv * (acc[mf][g][half * 2]     + sbias[cl]));
                    atomicAdd(&orow[cl + 1], wv * (acc[mf][g][half * 2 + 1] + sbias[cl + 1]));
                }
            }
        }
}

// ---------------------------------------------------------------
extern "C" void kernel_launch(void* const* d_in, const int* in_sizes, int n_in,
                              void* d_out, int out_size) {
    const float* x  = (const float*)d_in[0];
    const float* Wg = (const float*)d_in[1];
    const float* bg = (const float*)d_in[2];
    const float* W1 = (const float*)d_in[3];
    const float* b1 = (const float*)d_in[4];
    const float* W2 = (const float*)d_in[5];
    const float* b2 = (const float*)d_in[6];
    float* out = (float*)d_out;

    cudaFuncSetAttribute(ffn1_hmma, cudaFuncAttributeMaxDynamicSharedMemorySize, SMEM_BYTES);
    cudaFuncSetAttribute(ffn2_hmma, cudaFuncAttributeMaxDynamicSharedMemorySize, SMEM_BYTES);

    uint4* w1pk; cudaGetSymbolAddress((void**)&w1pk, g_w1pk);
    uint4* w2pk; cudaGetSymbolAddress((void**)&w2pk, g_w2pk);

    zero_kernel<<<NT * DM / 4 / 256, 256>>>(out);
    gate_kernel<<<1024, 256>>>(x, Wg, bg);
    offsets_kernel<<<1, 32>>>();
    // W1 [E][DM(k)][FF(n)] -> packed [e][n][k/32][4]
    wtrans_pack<<<dim3(FF / 32, DM / 32, NE), 256>>>(W1, w1pk, DM, FF);
    // W2 [E][FF(k)][DM(n)] -> packed [e][n][k/32][4]
    wtrans_pack<<<dim3(DM / 32, FF / 32, NE), 256>>>(W2, w2pk, FF, DM);

    ffn1_hmma<<<dim3(FF / 128, NT / 128, NE), 256, SMEM_BYTES>>>(x, b1);
    ffn2_hmma<<<dim3(DM / 128, NT / 128, NE), 256, SMEM_BYTES>>>(b2, out);
}

// round 17
// speedup vs baseline: 1.4313x; 1.2189x over previous
#include <cuda_runtime.h>
#include <cuda_fp16.h>
#include <math.h>
#include <stdint.h>

#define NT 8192
#define DM 1024
#define FF 4096
#define NE 8
#define TOTAL_ROWS (NT * 2)
#define KCH1 (DM / 32)      // k32 chunks in W1 pack
#define KCH2 (FF / 32)
#define NST1 (DM / 64)      // 16 k64 stages GEMM1
#define NST2 (FF / 64)      // 64 k64 stages GEMM2

// smem (uint4 units): header 128; per stage A[128][17] (16 data+1 pad), B[128][9]
#define AROW 17
#define BROW 9
#define HDR4 128
#define ATILE4 (128 * AROW)             // 2176
#define BTILE4 (128 * BROW)             // 1152
#define STAGE4 (ATILE4 + BTILE4)        // 3328
#define SMEM_BYTES ((HDR4 + 2 * STAGE4) * 16)   // 108544 B

// ---------------- scratch (device globals; no runtime alloc) ----------------
__device__ int   g_cnt[NE];
__device__ int   g_off[NE];
__device__ int   g_tok[NE * NT];
__device__ float g_w  [NE * NT];
// packed split-fp16 h: [row][FF/32 chunks][8 uint4]; padded 128 rows
__device__ uint4 g_hpk[(size_t)(TOTAL_ROWS + 128) * (KCH2 * 8)];
// packed fp16 weights (hi only), fragment-ordered: [e][n][k/32][4] uint4
__device__ uint4 g_w1pk[(size_t)NE * FF * KCH1 * 4];
__device__ uint4 g_w2pk[(size_t)NE * DM * KCH2 * 4];

// ---------------- fp16 mma.sync (validated R16) ----------------
__device__ __forceinline__ void mma_f16(float (&d)[4], const uint32_t (&a)[4],
                                        uint32_t b0, uint32_t b1) {
    asm volatile("mma.sync.aligned.m16n8k16.row.col.f32.f16.f16.f32 "
        "{%0,%1,%2,%3}, {%4,%5,%6,%7}, {%8,%9}, {%0,%1,%2,%3};"
        : "+f"(d[0]), "+f"(d[1]), "+f"(d[2]), "+f"(d[3])
        : "r"(a[0]), "r"(a[1]), "r"(a[2]), "r"(a[3]), "r"(b0), "r"(b1));
}

__device__ __forceinline__ void split2h(float v0, float v1, uint32_t& hi, uint32_t& lo) {
    __half2 h = __floats2half2_rn(v0, v1);
    float r0 = v0 - __half2float(__low2half(h));
    float r1 = v1 - __half2float(__high2half(h));
    __half2 l = __floats2half2_rn(r0, r1);
    hi = *reinterpret_cast<uint32_t*>(&h);
    lo = *reinterpret_cast<uint32_t*>(&l);
}

// pack 16 consecutive fp32 k (4 float4) -> 4 uint4: slot q = {hi(q),hi(q+4),lo(q),lo(q+4)}
__device__ __forceinline__ void pack16h(uint4 (&dst)[4], const float4 (&v)[4]) {
    const float f[16] = {v[0].x, v[0].y, v[0].z, v[0].w,
                         v[1].x, v[1].y, v[1].z, v[1].w,
                         v[2].x, v[2].y, v[2].z, v[2].w,
                         v[3].x, v[3].y, v[3].z, v[3].w};
#pragma unroll
    for (int q = 0; q < 4; q++) {
        uint32_t h0, l0, h1, l1;
        split2h(f[2 * q],     f[2 * q + 1], h0, l0);
        split2h(f[2 * q + 8], f[2 * q + 9], h1, l1);
        dst[q].x = h0; dst[q].y = h1; dst[q].z = l0; dst[q].w = l1;
    }
}

// ---------------- zero counts + output ----------------
__global__ void zero_kernel(float* __restrict__ out) {
    int i = blockIdx.x * blockDim.x + threadIdx.x;
    if (i < NE) g_cnt[i] = 0;
    float4* o4 = reinterpret_cast<float4*>(out);
    if (i < NT * DM / 4) o4[i] = make_float4(0.f, 0.f, 0.f, 0.f);
}

// ---------------- gate (validated R1) ----------------
__global__ void gate_kernel(const float* __restrict__ x,
                            const float* __restrict__ Wg,
                            const float* __restrict__ bg) {
    int gtid = blockIdx.x * blockDim.x + threadIdx.x;
    int t = gtid >> 5, lane = gtid & 31;
    if (t >= NT) return;
    const float* xr = x + (size_t)t * DM;
    float acc[NE];
#pragma unroll
    for (int e = 0; e < NE; e++) acc[e] = 0.f;
    for (int k = lane; k < DM; k += 32) {
        float xv = xr[k];
        const float* wr = Wg + k * NE;
#pragma unroll
        for (int e = 0; e < NE; e++) acc[e] += xv * wr[e];
    }
#pragma unroll
    for (int s = 16; s > 0; s >>= 1)
#pragma unroll
        for (int e = 0; e < NE; e++) acc[e] += __shfl_xor_sync(0xffffffffu, acc[e], s);
    if (lane == 0) {
#pragma unroll
        for (int e = 0; e < NE; e++) acc[e] += bg[e];
        float mx = acc[0];
#pragma unroll
        for (int e = 1; e < NE; e++) mx = fmaxf(mx, acc[e]);
        float s = 0.f;
#pragma unroll
        for (int e = 0; e < NE; e++) { acc[e] = expf(acc[e] - mx); s += acc[e]; }
        float inv = 1.f / s;
#pragma unroll
        for (int e = 0; e < NE; e++) acc[e] *= inv;
        int i0 = 0;
#pragma unroll
        for (int e = 1; e < NE; e++) if (acc[e] > acc[i0]) i0 = e;
        int i1 = (i0 == 0) ? 1 : 0;
#pragma unroll
        for (int e = 0; e < NE; e++) if (e != i0 && acc[e] > acc[i1]) i1 = e;
        float s2 = acc[i0] + acc[i1] + 1e-9f;
        int p0 = atomicAdd(&g_cnt[i0], 1);
        g_tok[i0 * NT + p0] = t;  g_w[i0 * NT + p0] = acc[i0] / s2;
        int p1 = atomicAdd(&g_cnt[i1], 1);
        g_tok[i1 * NT + p1] = t;  g_w[i1 * NT + p1] = acc[i1] / s2;
    }
}

__global__ void offsets_kernel() {
    if (threadIdx.x == 0 && blockIdx.x == 0) {
        int s = 0;
#pragma unroll
        for (int e = 0; e < NE; e++) { g_off[e] = s; s += g_cnt[e]; }
    }
}

// ---- transpose + fp16 pack: W [E][R=k][C=n] -> [e][n][k/32][4] uint4 (validated R16) ----
__global__ void wtrans_pack(const float* __restrict__ in, uint4* __restrict__ out,
                            int R, int C) {
    __shared__ float t[32][33];
    int e = blockIdx.z, c0 = blockIdx.x * 32, r0 = blockIdx.y * 32;
    const float* ie = in + (size_t)e * R * C;
    int tx = threadIdx.x & 31, ty = threadIdx.x >> 5;
#pragma unroll
    for (int i = 0; i < 4; i++)
        t[ty + i * 8][tx] = ie[(size_t)(r0 + ty + i * 8) * C + c0 + tx];   // t[k][n]
    __syncthreads();
    if (threadIdx.x < 128) {
        int nn = threadIdx.x >> 2, q = threadIdx.x & 3;
        __half2 P0 = __floats2half2_rn(t[2 * q][nn],      t[2 * q + 1][nn]);
        __half2 P1 = __floats2half2_rn(t[2 * q + 8][nn],  t[2 * q + 9][nn]);
        __half2 P2 = __floats2half2_rn(t[2 * q + 16][nn], t[2 * q + 17][nn]);
        __half2 P3 = __floats2half2_rn(t[2 * q + 24][nn], t[2 * q + 25][nn]);
        uint4 o;
        o.x = *reinterpret_cast<uint32_t*>(&P0);
        o.y = *reinterpret_cast<uint32_t*>(&P1);
        o.z = *reinterpret_cast<uint32_t*>(&P2);
        o.w = *reinterpret_cast<uint32_t*>(&P3);
        out[(((size_t)e * C + c0 + nn) * (R / 32) + (r0 >> 5)) * 4 + q] = o;
    }
}

// ---- compute one k64 stage: warp tile 32x32; 24 LDS.128 + 64 MMA per warp ----
__device__ __forceinline__ void compute_stage64(const uint4* __restrict__ A4,
                                                const uint4* __restrict__ B4,
                                                int wm, int wn, int lid,
                                                float (&acc)[2][4][4]) {
    const int qr = lid >> 2, q = lid & 3;
#pragma unroll
    for (int c2 = 0; c2 < 2; c2++) {             // k32 chunk within stage
        uint4 V[4];
#pragma unroll
        for (int g = 0; g < 4; g++)
            V[g] = B4[(wn + g * 8 + qr) * BROW + c2 * 4 + q];
#pragma unroll
        for (int s2 = 0; s2 < 2; s2++) {         // k16 within chunk
            uint32_t ah[2][4], al[2][4];
#pragma unroll
            for (int mf = 0; mf < 2; mf++) {
                uint4 U1 = A4[(wm + mf * 16 + qr) * AROW + (c2 * 2 + s2) * 4 + q];
                uint4 U2 = A4[(wm + mf * 16 + qr + 8) * AROW + (c2 * 2 + s2) * 4 + q];
                ah[mf][0] = U1.x; ah[mf][1] = U2.x; ah[mf][2] = U1.y; ah[mf][3] = U2.y;
                al[mf][0] = U1.z; al[mf][1] = U2.z; al[mf][2] = U1.w; al[mf][3] = U2.w;
            }
#pragma unroll
            for (int g = 0; g < 4; g++) {
                uint32_t b0 = s2 ? V[g].z : V[g].x;
                uint32_t b1 = s2 ? V[g].w : V[g].y;
                mma_f16(acc[0][g], ah[0], b0, b1);
                mma_f16(acc[1][g], ah[1], b0, b1);
                mma_f16(acc[0][g], al[0], b0, b1);
                mma_f16(acc[1][g], al[1], b0, b1);
            }
        }
    }
}

// ================= GEMM1: h = gelu(x[tok] @ W1 + b1) -> packed h =================
__global__ __launch_bounds__(512, 1) void ffn1_hmma(const float* __restrict__ x,
                                                    const float* __restrict__ b1) {
    extern __shared__ uint4 sm4[];
    const int e = blockIdx.z;
    const int cnt = g_cnt[e];
    const int mbase = blockIdx.y * 128;
    if (mbase >= cnt) return;
    const int nbase = blockIdx.x * 128;

    const int tid = threadIdx.x, wid = tid >> 5, lid = tid & 31;
    const int wm = (wid & 3) * 32, wn = (wid >> 2) * 32;

    int*   stok  = reinterpret_cast<int*>(sm4);
    float* sbias = reinterpret_cast<float*>(sm4) + 128;

    if (tid < 128) {
        int mi = mbase + tid;
        stok[tid]  = (mi < cnt) ? g_tok[e * NT + mi] : g_tok[e * NT + mbase];
        sbias[tid] = b1[e * FF + nbase + tid];
    }
    __syncthreads();

    // staging maps: A thread -> (row, kq quarter of 16 k); B thread -> (row, j2)
    const int row = tid >> 2, kq = tid & 3;
    const float* arow = x + (size_t)stok[row] * DM + kq * 16;
    const uint4* brow = g_w1pk + ((size_t)e * FF + nbase + row) * (KCH1 * 4);
    const int aslot = row * AROW + kq * 4;
    const int bslot = row * BROW + kq * 2;

    float acc[2][4][4];
#pragma unroll
    for (int i = 0; i < 2; i++)
#pragma unroll
        for (int j = 0; j < 4; j++)
#pragma unroll
            for (int k = 0; k < 4; k++) acc[i][j][k] = 0.f;

    float4 ra[4];
    uint4  rb[2];
#pragma unroll
    for (int j = 0; j < 4; j++) ra[j] = *reinterpret_cast<const float4*>(arow + j * 4);
    rb[0] = brow[kq * 2]; rb[1] = brow[kq * 2 + 1];

    int buf = 0;
    for (int c = 0; c < NST1; c++) {
        uint4* As = sm4 + HDR4 + buf * STAGE4;
        uint4* Bs = As + ATILE4;
        uint4 pa[4];
        pack16h(pa, ra);
#pragma unroll
        for (int q = 0; q < 4; q++) As[aslot + q] = pa[q];
        Bs[bslot] = rb[0]; Bs[bslot + 1] = rb[1];
        __syncthreads();
        if (c + 1 < NST1) {   // prefetch next stage; overlaps compute
#pragma unroll
            for (int j = 0; j < 4; j++)
                ra[j] = *reinterpret_cast<const float4*>(arow + (c + 1) * 64 + j * 4);
            rb[0] = brow[(c + 1) * 8 + kq * 2];
            rb[1] = brow[(c + 1) * 8 + kq * 2 + 1];
        }
        compute_stage64(sm4 + HDR4 + buf * STAGE4,
                        sm4 + HDR4 + buf * STAGE4 + ATILE4, wm, wn, lid, acc);
        buf ^= 1;
    }

    // epilogue: bias + exact GELU -> packed split-fp16 h (2 STG.128 per mf/half)
    const int hoff = g_off[e];
    const int qr = lid >> 2, ql = lid & 3, c2v = ql * 2;
    const int chunk = (nbase + wn) >> 5;   // k32 chunk of h row covered by this warp
#pragma unroll
    for (int mf = 0; mf < 2; mf++)
#pragma unroll
        for (int half = 0; half < 2; half++) {
            int m = mbase + wm + mf * 16 + qr + half * 8;
            if (m < cnt) {
                float gv[4];
#pragma unroll
                for (int g = 0; g < 4; g++) {
                    int cl = wn + g * 8 + c2v;
                    float v0 = acc[mf][g][half * 2]     + sbias[cl];
                    float v1 = acc[mf][g][half * 2 + 1] + sbias[cl + 1];
                    gv[g] = 0.f;  // placeholder; packed below
                    // compute gelu into temporaries via split below
                    float g0 = 0.5f * v0 * (1.f + erff(v0 * 0.70710678118654752f));
                    float g1 = 0.5f * v1 * (1.f + erff(v1 * 0.70710678118654752f));
                    // stash packed words in gv slots via reinterpret (2 words per g)
                    uint32_t hw, lw;
                    split2h(g0, g1, hw, lw);
                    ((uint32_t*)gv)[g] = hw;        // reuse gv as hi-word array
                    // lo words kept in local array below
                    if (g == 0) { }
                    // store lo separately:
                    // (use a second array)
                    // -- implemented with explicit arrays below instead
                    (void)lw;
                }
                // recompute cleanly with explicit arrays (compiler folds duplicates)
                uint32_t hwv[4], lwv[4];
#pragma unroll
                for (int g = 0; g < 4; g++) {
                    int cl = wn + g * 8 + c2v;
                    float v0 = acc[mf][g][half * 2]     + sbias[cl];
                    float v1 = acc[mf][g][half * 2 + 1] + sbias[cl + 1];
                    float g0 = 0.5f * v0 * (1.f + erff(v0 * 0.70710678118654752f));
                    float g1 = 0.5f * v1 * (1.f + erff(v1 * 0.70710678118654752f));
                    split2h(g0, g1, hwv[g], lwv[g]);
                }
                uint4* hrow = g_hpk + (size_t)(hoff + m) * (KCH2 * 8) + chunk * 8 + ql;
                uint4 o0, o1;
                o0.x = hwv[0]; o0.y = hwv[1]; o0.z = lwv[0]; o0.w = lwv[1];   // kh=0 (g0,g1)
                o1.x = hwv[2]; o1.y = hwv[3]; o1.z = lwv[2]; o1.w = lwv[3];   // kh=1 (g2,g3)
                hrow[0] = o0;
                hrow[4] = o1;
            }
        }
}

// ================= GEMM2: out[tok] += w * (h @ W2 + b2) =================
__global__ __launch_bounds__(512, 1) void ffn2_hmma(const float* __restrict__ b2,
                                                    float* __restrict__ out) {
    extern __shared__ uint4 sm4[];
    const int e = blockIdx.z;
    const int cnt = g_cnt[e];
    const int mbase = blockIdx.y * 128;
    if (mbase >= cnt) return;
    const int nbase = blockIdx.x * 128;

    const int tid = threadIdx.x, wid = tid >> 5, lid = tid & 31;
    const int wm = (wid & 3) * 32, wn = (wid >> 2) * 32;

    int*   stok  = reinterpret_cast<int*>(sm4);
    float* sbias = reinterpret_cast<float*>(sm4) + 128;
    float* swt   = reinterpret_cast<float*>(sm4) + 256;

    if (tid < 128) {
        int mi = mbase + tid;
        bool v = mi < cnt;
        stok[tid]  = v ? g_tok[e * NT + mi] : 0;
        swt[tid]   = v ? g_w  [e * NT + mi] : 0.f;
        sbias[tid] = b2[e * DM + nbase + tid];
    }
    __syncthreads();

    const int hoff = g_off[e];
    const int row = tid >> 2, kq = tid & 3;
    const uint4* arow = g_hpk + (size_t)(hoff + mbase + row) * (KCH2 * 8);   // padded
    const uint4* brow = g_w2pk + ((size_t)e * DM + nbase + row) * (KCH2 * 4);
    const int aslot = row * AROW + kq * 4;
    const int bslot = row * BROW + kq * 2;

    float acc[2][4][4];
#pragma unroll
    for (int i = 0; i < 2; i++)
#pragma unroll
        for (int j = 0; j < 4; j++)
#pragma unroll
            for (int k = 0; k < 4; k++) acc[i][j][k] = 0.f;

    uint4 ca[4], rb[2];
#pragma unroll
    for (int j = 0; j < 4; j++) ca[j] = arow[kq * 4 + j];
    rb[0] = brow[kq * 2]; rb[1] = brow[kq * 2 + 1];

    int buf = 0;
    for (int c = 0; c < NST2; c++) {
        uint4* As = sm4 + HDR4 + buf * STAGE4;
        uint4* Bs = As + ATILE4;
#pragma unroll
        for (int q = 0; q < 4; q++) As[aslot + q] = ca[q];
        Bs[bslot] = rb[0]; Bs[bslot + 1] = rb[1];
        __syncthreads();
        if (c + 1 < NST2) {
#pragma unroll
            for (int j = 0; j < 4; j++)
                ca[j] = arow[(c + 1) * 16 + kq * 4 + j];
            rb[0] = brow[(c + 1) * 8 + kq * 2];
            rb[1] = brow[(c + 1) * 8 + kq * 2 + 1];
        }
        compute_stage64(sm4 + HDR4 + buf * STAGE4,
                        sm4 + HDR4 + buf * STAGE4 + ATILE4, wm, wn, lid, acc);
        buf ^= 1;
    }

    // epilogue: bias + gate-weighted scatter (validated)
    const int qr = lid >> 2, c2v = (lid & 3) * 2;
#pragma unroll
    for (int mf = 0; mf < 2; mf++)
#pragma unroll
        for (int half = 0; half < 2; half++) {
            int mloc = wm + mf * 16 + qr + half * 8;
            int m = mbase + mloc;
            if (m < cnt) {
                int   tok = stok[mloc];
                float wv  = swt[mloc];
                float* orow = out + (size_t)tok * DM + nbase;
#pragma unroll
                for (int g = 0; g < 4; g++) {
                    int cl = wn + g * 8 + c2v;
                    atomicAdd(&orow[cl],     wv * (acc[mf][g][half * 2]     + sbias[cl]));
                    atomicAdd(&orow[cl + 1], wv * (acc[mf][g][half * 2 + 1] + sbias[cl + 1]));
                }
            }
        }
}

// ---------------------------------------------------------------
extern "C" void kernel_launch(void* const* d_in, const int* in_sizes, int n_in,
                              void* d_out, int out_size) {
    const float* x  = (const float*)d_in[0];
    const float* Wg = (const float*)d_in[1];
    const float* bg = (const float*)d_in[2];
    const float* W1 = (const float*)d_in[3];
    const float* b1 = (const float*)d_in[4];
    const float* W2 = (const float*)d_in[5];
    const float* b2 = (const float*)d_in[6];
    float* out = (float*)d_out;

    cudaFuncSetAttribute(ffn1_hmma, cudaFuncAttributeMaxDynamicSharedMemorySize, SMEM_BYTES);
    cudaFuncSetAttribute(ffn2_hmma, cudaFuncAttributeMaxDynamicSharedMemorySize, SMEM_BYTES);

    uint4* w1pk; cudaGetSymbolAddress((void**)&w1pk, g_w1pk);
    uint4* w2pk; cudaGetSymbolAddress((void**)&w2pk, g_w2pk);

    zero_kernel<<<NT * DM / 4 / 256, 256>>>(out);
    gate_kernel<<<1024, 256>>>(x, Wg, bg);
    offsets_kernel<<<1, 32>>>();
    wtrans_pack<<<dim3(FF / 32, DM / 32, NE), 256>>>(W1, w1pk, DM, FF);
    wtrans_pack<<<dim3(DM / 32, FF / 32, NE), 256>>>(W2, w2pk, FF, DM);

    ffn1_hmma<<<dim3(FF / 128, NT / 128, NE), 512, SMEM_BYTES>>>(x, b1);
    ffn2_hmma<<<dim3(DM / 128, NT / 128, NE), 512, SMEM_BYTES>>>(b2, out);
}